// round 1
// baseline (speedup 1.0000x reference)
#include <cuda_runtime.h>
#include <cuda_bf16.h>
#include <math.h>

// Problem constants
#define BB 4
#define NN 1024
#define DD 1024
#define HH 16
#define HDIM 64
#define TT (BB*NN)          // 4096 tokens
#define LD65 65

// ---------------- scratch (device globals; no allocs allowed) ----------------
__device__ float g_lx [TT*DD];
__device__ float g_qs [TT*DD];
__device__ float g_ks [TT*DD];
__device__ float g_vs [TT*DD];
__device__ float g_qh [BB*HH*NN*LD65];   // lifted q (time negated); reused for mid
__device__ float g_kh [BB*HH*NN*LD65];
__device__ float g_vh [BB*HH*NN*LD65];
__device__ float g_sc [(long)BB*HH*NN*NN]; // 256 MB scores
__device__ float g_cat[TT*(HH*LD65)];    // 4096 x 1040
__device__ float g_axs[TT*1023];
__device__ float g_x1 [TT*DD];
__device__ float g_h1 [TT*DD];
__device__ float g_fc [TT*4096];
__device__ float g_pjs[TT*1023];

// ---------------- block reductions ----------------
__device__ __forceinline__ float blk_sum(float v, float* sbuf) {
    int tid = threadIdx.x;
    #pragma unroll
    for (int o = 16; o > 0; o >>= 1) v += __shfl_down_sync(0xffffffffu, v, o);
    if ((tid & 31) == 0) sbuf[tid >> 5] = v;
    __syncthreads();
    if (tid < 32) {
        int nw = (blockDim.x + 31) >> 5;
        float x = (tid < nw) ? sbuf[tid] : 0.f;
        #pragma unroll
        for (int o = 16; o > 0; o >>= 1) x += __shfl_down_sync(0xffffffffu, x, o);
        if (tid == 0) sbuf[0] = x;
    }
    __syncthreads();
    float r = sbuf[0];
    __syncthreads();
    return r;
}

__device__ __forceinline__ float blk_max(float v, float* sbuf) {
    int tid = threadIdx.x;
    #pragma unroll
    for (int o = 16; o > 0; o >>= 1) v = fmaxf(v, __shfl_down_sync(0xffffffffu, v, o));
    if ((tid & 31) == 0) sbuf[tid >> 5] = v;
    __syncthreads();
    if (tid < 32) {
        int nw = (blockDim.x + 31) >> 5;
        float x = (tid < nw) ? sbuf[tid] : -3.4e38f;
        #pragma unroll
        for (int o = 16; o > 0; o >>= 1) x = fmaxf(x, __shfl_down_sync(0xffffffffu, x, o));
        if (tid == 0) sbuf[0] = x;
    }
    __syncthreads();
    float r = sbuf[0];
    __syncthreads();
    return r;
}

// ---------------- generic tiled SGEMM ----------------
// C[m, c0+n] = alpha * sum_k A[m,k]*B(k,n) + cadd + (BIAS ? bias[n] : 0)
// TRANSB=false: B is (K,N) row-major, B(k,n)=B[k*ldb+n]
// TRANSB=true : B is (N,K) row-major, B(k,n)=B[n*ldb+k]
template<bool TRANSB, bool BIAS>
__global__ __launch_bounds__(256)
void sgemm_kernel(const float* __restrict__ A, const float* __restrict__ B,
                  const float* __restrict__ bias, float* __restrict__ C,
                  int M, int N, int K, int lda, int ldb, int ldc, int c0,
                  long long sA, long long sB, long long sC,
                  float alpha, float cadd)
{
    long long bz = blockIdx.z;
    A += bz * sA; B += bz * sB; C += bz * sC;
    int m0 = blockIdx.y * 128, n0 = blockIdx.x * 128;

    __shared__ float As[8][128];
    __shared__ float Bs[8][128];

    int tid = threadIdx.x;
    int tx = tid & 15, ty = tid >> 4;

    float acc[8][8];
    #pragma unroll
    for (int i = 0; i < 8; i++)
        #pragma unroll
        for (int j = 0; j < 8; j++) acc[i][j] = 0.f;

    for (int kt = 0; kt < K; kt += 8) {
        #pragma unroll
        for (int i = 0; i < 4; i++) {
            int e = tid + i * 256;
            int m = e >> 3, kk = e & 7;
            int gm = m0 + m, gk = kt + kk;
            As[kk][m] = (gm < M && gk < K) ? A[(long long)gm * lda + gk] : 0.f;
        }
        #pragma unroll
        for (int i = 0; i < 4; i++) {
            int e = tid + i * 256;
            int n, kk;
            if (TRANSB) { n = e >> 3;  kk = e & 7; }
            else        { n = e & 127; kk = e >> 7; }
            int gn = n0 + n, gk = kt + kk;
            float v = 0.f;
            if (gn < N && gk < K)
                v = TRANSB ? B[(long long)gn * ldb + gk] : B[(long long)gk * ldb + gn];
            Bs[kk][n] = v;
        }
        __syncthreads();

        #pragma unroll
        for (int kk = 0; kk < 8; kk++) {
            float a[8], b[8];
            #pragma unroll
            for (int i = 0; i < 8; i++) a[i] = As[kk][ty * 8 + i];
            #pragma unroll
            for (int j = 0; j < 8; j++) b[j] = Bs[kk][tx * 8 + j];
            #pragma unroll
            for (int i = 0; i < 8; i++)
                #pragma unroll
                for (int j = 0; j < 8; j++)
                    acc[i][j] += a[i] * b[j];
        }
        __syncthreads();
    }

    #pragma unroll
    for (int i = 0; i < 8; i++) {
        int gm = m0 + ty * 8 + i;
        if (gm >= M) continue;
        #pragma unroll
        for (int j = 0; j < 8; j++) {
            int gn = n0 + tx * 8 + j;
            if (gn >= N) continue;
            float v = alpha * acc[i][j] + cadd;
            if (BIAS) v += bias[gn];
            C[(long long)gm * ldc + c0 + gn] = v;
        }
    }
}

// ---------------- Lorentz layernorm: (T,1024) -> (T,1024) lifted ----------------
__global__ __launch_bounds__(256)
void k_ln(const float* __restrict__ x, const float* __restrict__ g,
          const float* __restrict__ b, float* __restrict__ out)
{
    __shared__ float sbuf[32];
    int t = blockIdx.x, tid = threadIdx.x;
    const float* xs = x + (long long)t * DD + 1;
    float sv[4]; float s1 = 0.f, s2 = 0.f;
    #pragma unroll
    for (int j = 0; j < 4; j++) {
        int i = tid + j * 256;
        sv[j] = 0.f;
        if (i < 1023) { sv[j] = xs[i]; s1 += sv[j]; s2 += sv[j] * sv[j]; }
    }
    s1 = blk_sum(s1, sbuf);
    s2 = blk_sum(s2, sbuf);
    float mu = s1 * (1.f / 1023.f);
    float var = s2 * (1.f / 1023.f) - mu * mu;
    float rstd = rsqrtf(var + 1e-5f);
    float q = 0.f;
    #pragma unroll
    for (int j = 0; j < 4; j++) {
        int i = tid + j * 256;
        if (i < 1023) {
            float y = (sv[j] - mu) * rstd * g[i] + b[i];
            out[(long long)t * DD + 1 + i] = y;
            q += y * y;
        }
    }
    q = blk_sum(q, sbuf);
    if (tid == 0) out[(long long)t * DD] = sqrtf(q + 1.f);
}

// ---------------- lift heads: (T,1024) -> (B,H,N,65), time*sign ----------------
__global__ __launch_bounds__(512)
void k_lift(const float* __restrict__ S, float* __restrict__ Oh, float sign)
{
    int t = blockIdx.x;
    int b = t / NN, n = t % NN;
    int w = threadIdx.x >> 5, lane = threadIdx.x & 31;
    const float* src = S + (long long)t * DD + w * HDIM;
    float v0 = src[lane], v1 = src[lane + 32];
    float ss = v0 * v0 + v1 * v1;
    #pragma unroll
    for (int o = 16; o > 0; o >>= 1) ss += __shfl_down_sync(0xffffffffu, ss, o);
    ss = __shfl_sync(0xffffffffu, ss, 0);
    float* dst = Oh + ((long long)(b * HH + w) * NN + n) * LD65;
    dst[1 + lane] = v0;
    dst[33 + lane] = v1;
    if (lane == 0) dst[0] = sign * sqrtf(ss + 1.f);
}

// ---------------- softmax over last dim (rows of 1024) ----------------
__global__ __launch_bounds__(256)
void k_softmax(float* __restrict__ sc)
{
    __shared__ float sbuf[32];
    float* row = sc + (long long)blockIdx.x * NN;
    int tid = threadIdx.x;
    float v[4];
    float m = -3.4e38f;
    #pragma unroll
    for (int j = 0; j < 4; j++) { v[j] = row[tid + j * 256]; m = fmaxf(m, v[j]); }
    m = blk_max(m, sbuf);
    float s = 0.f;
    #pragma unroll
    for (int j = 0; j < 4; j++) { v[j] = __expf(v[j] - m); s += v[j]; }
    s = blk_sum(s, sbuf);
    float inv = 1.f / s;
    #pragma unroll
    for (int j = 0; j < 4; j++) row[tid + j * 256] = v[j] * inv;
}

// ---------------- normalize mid + concat heads ----------------
__global__ __launch_bounds__(512)
void k_normcat(const float* __restrict__ mid, float* __restrict__ cat)
{
    int t = blockIdx.x;
    int b = t / NN, n = t % NN;
    int w = threadIdx.x >> 5, lane = threadIdx.x & 31;
    const float* src = mid + ((long long)(b * HH + w) * NN + n) * LD65;
    float tm = src[0];
    float a0 = src[1 + lane], a1 = src[33 + lane];
    float ss = a0 * a0 + a1 * a1;
    #pragma unroll
    for (int o = 16; o > 0; o >>= 1) ss += __shfl_down_sync(0xffffffffu, ss, o);
    ss = __shfl_sync(0xffffffffu, ss, 0);
    float inv = rsqrtf(fmaxf(tm * tm - ss, 1e-8f));
    float* dst = cat + (long long)t * (HH * LD65) + w * LD65;
    dst[1 + lane] = a0 * inv;
    dst[33 + lane] = a1 * inv;
    if (lane == 0) dst[0] = tm * inv;
}

// ---------------- gelu (exact) on cols 1..4095 + lift into col 0 ----------------
__global__ __launch_bounds__(256)
void k_gelu(float* __restrict__ fc)
{
    __shared__ float sbuf[32];
    int t = blockIdx.x, tid = threadIdx.x;
    float* row = fc + (long long)t * 4096;
    float q = 0.f;
    #pragma unroll
    for (int j = 0; j < 16; j++) {
        int i = 1 + tid + j * 256;
        if (i < 4096) {
            float x = row[i];
            float g = 0.5f * x * (1.f + erff(x * 0.70710678118654752f));
            row[i] = g;
            q += g * g;
        }
    }
    q = blk_sum(q, sbuf);
    if (tid == 0) row[0] = sqrtf(q + 1.f);
}

// ---------------- Lorentz residual: out = (x + w*lift(s)) / sqrt(-<z,z>) ----------------
__global__ __launch_bounds__(256)
void k_lresnet(const float* __restrict__ xin, const float* __restrict__ spart,
               const float* __restrict__ wp, float* __restrict__ out)
{
    __shared__ float sbuf[32];
    int t = blockIdx.x, tid = threadIdx.x;
    float w = wp[0];
    const float* xr = xin + (long long)t * DD;
    const float* ar = spart + (long long)t * 1023;
    float xs[4], as[4];
    float sa = 0.f;
    #pragma unroll
    for (int j = 0; j < 4; j++) {
        int i = tid + j * 256;
        xs[j] = 0.f; as[j] = 0.f;
        if (i < 1023) { xs[j] = xr[1 + i]; as[j] = ar[i]; sa += as[j] * as[j]; }
    }
    sa = blk_sum(sa, sbuf);
    float axt = sqrtf(sa + 1.f);
    float zt = xr[0] + w * axt;
    float sz = 0.f;
    #pragma unroll
    for (int j = 0; j < 4; j++) {
        int i = tid + j * 256;
        if (i < 1023) { xs[j] = xs[j] + w * as[j]; sz += xs[j] * xs[j]; }
    }
    sz = blk_sum(sz, sbuf);
    float inv = rsqrtf(fmaxf(zt * zt - sz, 1e-8f));
    if (tid == 0) out[(long long)t * DD] = zt * inv;
    #pragma unroll
    for (int j = 0; j < 4; j++) {
        int i = tid + j * 256;
        if (i < 1023) out[(long long)t * DD + 1 + i] = xs[j] * inv;
    }
}

// ---------------- host launch ----------------
extern "C" void kernel_launch(void* const* d_in, const int* in_sizes, int n_in,
                              void* d_out, int out_size)
{
    const float* x   = (const float*)d_in[0];
    const float* g1  = (const float*)d_in[1];
    const float* b1  = (const float*)d_in[2];
    const float* Wq  = (const float*)d_in[3];
    const float* bq  = (const float*)d_in[4];
    const float* Wk  = (const float*)d_in[5];
    const float* bk  = (const float*)d_in[6];
    const float* Wv  = (const float*)d_in[7];
    const float* bv  = (const float*)d_in[8];
    const float* Wo  = (const float*)d_in[9];
    const float* bo  = (const float*)d_in[10];
    const float* g2  = (const float*)d_in[11];
    const float* b2  = (const float*)d_in[12];
    const float* Wfc = (const float*)d_in[13];
    const float* bfc = (const float*)d_in[14];
    const float* Wpj = (const float*)d_in[15];
    const float* bpj = (const float*)d_in[16];
    const float* w1  = (const float*)d_in[17];
    const float* w2  = (const float*)d_in[18];
    float* out = (float*)d_out;

    float *lx, *qs, *ks, *vs, *qh, *kh, *vh, *sc, *cat, *axs, *x1, *h1, *fc, *pjs;
    cudaGetSymbolAddress((void**)&lx,  g_lx);
    cudaGetSymbolAddress((void**)&qs,  g_qs);
    cudaGetSymbolAddress((void**)&ks,  g_ks);
    cudaGetSymbolAddress((void**)&vs,  g_vs);
    cudaGetSymbolAddress((void**)&qh,  g_qh);
    cudaGetSymbolAddress((void**)&kh,  g_kh);
    cudaGetSymbolAddress((void**)&vh,  g_vh);
    cudaGetSymbolAddress((void**)&sc,  g_sc);
    cudaGetSymbolAddress((void**)&cat, g_cat);
    cudaGetSymbolAddress((void**)&axs, g_axs);
    cudaGetSymbolAddress((void**)&x1,  g_x1);
    cudaGetSymbolAddress((void**)&h1,  g_h1);
    cudaGetSymbolAddress((void**)&fc,  g_fc);
    cudaGetSymbolAddress((void**)&pjs, g_pjs);

    // 1) LN1
    k_ln<<<TT, 256>>>(x, g1, b1, lx);

    // 2) QKV GEMMs: (4096,1024) x (1024,1024)
    {
        dim3 grid(DD / 128, TT / 128);
        sgemm_kernel<false, true><<<grid, 256>>>(lx, Wq, bq, qs, TT, DD, DD, DD, DD, DD, 0, 0, 0, 0, 1.f, 0.f);
        sgemm_kernel<false, true><<<grid, 256>>>(lx, Wk, bk, ks, TT, DD, DD, DD, DD, DD, 0, 0, 0, 0, 1.f, 0.f);
        sgemm_kernel<false, true><<<grid, 256>>>(lx, Wv, bv, vs, TT, DD, DD, DD, DD, DD, 0, 0, 0, 0, 1.f, 0.f);
    }

    // 3) lift heads (q time negated to fold Lorentz sign)
    k_lift<<<TT, 512>>>(qs, qh, -1.f);
    k_lift<<<TT, 512>>>(ks, kh,  1.f);
    k_lift<<<TT, 512>>>(vs, vh,  1.f);

    // 4) scores = (2 + 2*<q',k'>)/8, batched NT GEMM over 64 (b,h)
    {
        dim3 grid(NN / 128, NN / 128, BB * HH);
        sgemm_kernel<true, false><<<grid, 256>>>(qh, kh, nullptr, sc,
            NN, NN, LD65, LD65, LD65, NN, 0,
            (long long)NN * LD65, (long long)NN * LD65, (long long)NN * NN,
            0.25f, 0.25f);
    }

    // 5) softmax over rows
    k_softmax<<<BB * HH * NN, 256>>>(sc);

    // 6) mid = attn @ v_lift, batched NN GEMM (K=1024, N=65) -> reuse qh
    {
        dim3 grid(1, NN / 128, BB * HH);
        sgemm_kernel<false, false><<<grid, 256>>>(sc, vh, nullptr, qh,
            NN, LD65, NN, NN, LD65, LD65, 0,
            (long long)NN * NN, (long long)NN * LD65, (long long)NN * LD65,
            1.f, 0.f);
    }

    // 7) normalize mid + concat -> cat (4096,1040)
    k_normcat<<<TT, 512>>>(qh, cat);

    // 8) Wo GEMM: (4096,1040)x(1040,1023)+bo -> axs (ld 1023)
    {
        dim3 grid((1023 + 127) / 128, TT / 128);
        sgemm_kernel<false, true><<<grid, 256>>>(cat, Wo, bo, axs,
            TT, 1023, HH * LD65, HH * LD65, 1023, 1023, 0, 0, 0, 0, 1.f, 0.f);
    }

    // 9) lresnet1 -> x1
    k_lresnet<<<TT, 256>>>(x, axs, w1, x1);

    // 10) LN2
    k_ln<<<TT, 256>>>(x1, g2, b2, h1);

    // 11) Wfc GEMM: (4096,1024)x(1024,4095)+bfc -> fc cols 1..4095 (ld 4096)
    {
        dim3 grid((4095 + 127) / 128, TT / 128);
        sgemm_kernel<false, true><<<grid, 256>>>(h1, Wfc, bfc, fc,
            TT, 4095, DD, DD, 4095, 4096, 1, 0, 0, 0, 1.f, 0.f);
    }

    // 12) gelu + lift (in place, writes col 0)
    k_gelu<<<TT, 256>>>(fc);

    // 13) Wpj GEMM: (4096,4096)x(4096,1023)+bpj -> pjs (ld 1023)
    {
        dim3 grid((1023 + 127) / 128, TT / 128);
        sgemm_kernel<false, true><<<grid, 256>>>(fc, Wpj, bpj, pjs,
            TT, 1023, 4096, 4096, 1023, 1023, 0, 0, 0, 0, 1.f, 0.f);
    }

    // 14) lresnet2 -> out
    k_lresnet<<<TT, 256>>>(x1, pjs, w2, out);
}

// round 3
// speedup vs baseline: 3.8473x; 3.8473x over previous
#include <cuda_runtime.h>
#include <cuda_bf16.h>
#include <math.h>
#include <stdint.h>

// Problem constants
#define BB 4
#define NNTOK 1024
#define DDIM 1024
#define HH 16
#define TT (BB*NNTOK)     // 4096 tokens
#define BHN (BB*HH)       // 64

typedef __nv_bfloat16 bf16;

// ===================== scratch (device globals) =====================
__device__ __align__(128) bf16  g_lxh [TT*1024];
__device__ __align__(128) bf16  g_lxl [TT*1024];
__device__ __align__(128) bf16  g_WqTh[1024*1024];
__device__ __align__(128) bf16  g_WqTl[1024*1024];
__device__ __align__(128) bf16  g_WkTh[1024*1024];
__device__ __align__(128) bf16  g_WkTl[1024*1024];
__device__ __align__(128) bf16  g_WvTh[1024*1024];
__device__ __align__(128) bf16  g_WvTl[1024*1024];
__device__ __align__(128) bf16  g_WoTh[1024*1088];
__device__ __align__(128) bf16  g_WoTl[1024*1088];
__device__ __align__(128) bf16  g_WfcTh[4096*1024];
__device__ __align__(128) bf16  g_WfcTl[4096*1024];
__device__ __align__(128) bf16  g_WpjTh[1024*4096];
__device__ __align__(128) bf16  g_WpjTl[1024*4096];
__device__ __align__(128) float g_qs  [TT*1024];
__device__ __align__(128) float g_ks  [TT*1024];
__device__ __align__(128) float g_vs  [TT*1024];
__device__ __align__(128) bf16  g_qhh [BHN*1024*128];
__device__ __align__(128) bf16  g_qhl [BHN*1024*128];
__device__ __align__(128) bf16  g_khh [BHN*1024*128];
__device__ __align__(128) bf16  g_khl [BHN*1024*128];
__device__ __align__(128) bf16  g_vTh [BHN*128*1024];
__device__ __align__(128) bf16  g_vTl [BHN*128*1024];
__device__ __align__(128) float g_sc  [(size_t)BHN*1024*1024];  // 256MB
__device__ __align__(128) bf16  g_ph  [(size_t)BHN*1024*1024];  // probs hi
__device__ __align__(128) bf16  g_pl  [(size_t)BHN*1024*1024];  // probs lo
__device__ __align__(128) float g_mid [BHN*1024*65];
__device__ __align__(128) bf16  g_cath[TT*1088];
__device__ __align__(128) bf16  g_catl[TT*1088];
__device__ __align__(128) float g_axs [TT*1023];
__device__ __align__(128) float g_x1  [TT*1024];
__device__ __align__(128) bf16  g_h1h [TT*1024];
__device__ __align__(128) bf16  g_h1l [TT*1024];
__device__ __align__(128) float g_fcpre[(size_t)TT*4095];
__device__ __align__(128) bf16  g_fch [(size_t)TT*4096];
__device__ __align__(128) bf16  g_fcl [(size_t)TT*4096];
__device__ __align__(128) float g_pjs [TT*1023];

// ===================== PTX helpers =====================
__device__ __forceinline__ uint32_t smem_u32(const void* p) {
    uint32_t a;
    asm("{ .reg .u64 t; cvta.to.shared.u64 t, %1; cvt.u32.u64 %0, t; }" : "=r"(a) : "l"(p));
    return a;
}

#define CP_ASYNC16(dst, src) \
    asm volatile("cp.async.cg.shared.global [%0], [%1], 16;" :: "r"(dst), "l"(src))
#define CP_COMMIT() asm volatile("cp.async.commit_group;")
#define CP_WAIT1()  asm volatile("cp.async.wait_group 1;")
#define CP_WAIT0()  asm volatile("cp.async.wait_group 0;")

__device__ __forceinline__ void mma16816(float* c, const uint32_t* a, const uint32_t* b) {
    asm volatile(
        "mma.sync.aligned.m16n8k16.row.col.f32.bf16.bf16.f32 "
        "{%0,%1,%2,%3}, {%4,%5,%6,%7}, {%8,%9}, {%0,%1,%2,%3};"
        : "+f"(c[0]), "+f"(c[1]), "+f"(c[2]), "+f"(c[3])
        : "r"(a[0]), "r"(a[1]), "r"(a[2]), "r"(a[3]), "r"(b[0]), "r"(b[1]));
}

__device__ __forceinline__ void bsplit(float v, bf16& h, bf16& l) {
    h = __float2bfloat16(v);
    l = __float2bfloat16(v - __bfloat162float(h));
}

// ===================== block reductions =====================
__device__ __forceinline__ float blk_sum(float v, float* sbuf) {
    int tid = threadIdx.x;
    #pragma unroll
    for (int o = 16; o > 0; o >>= 1) v += __shfl_down_sync(0xffffffffu, v, o);
    if ((tid & 31) == 0) sbuf[tid >> 5] = v;
    __syncthreads();
    if (tid < 32) {
        int nw = (blockDim.x + 31) >> 5;
        float x = (tid < nw) ? sbuf[tid] : 0.f;
        #pragma unroll
        for (int o = 16; o > 0; o >>= 1) x += __shfl_down_sync(0xffffffffu, x, o);
        if (tid == 0) sbuf[0] = x;
    }
    __syncthreads();
    float r = sbuf[0];
    __syncthreads();
    return r;
}
__device__ __forceinline__ float blk_max(float v, float* sbuf) {
    int tid = threadIdx.x;
    #pragma unroll
    for (int o = 16; o > 0; o >>= 1) v = fmaxf(v, __shfl_down_sync(0xffffffffu, v, o));
    if ((tid & 31) == 0) sbuf[tid >> 5] = v;
    __syncthreads();
    if (tid < 32) {
        int nw = (blockDim.x + 31) >> 5;
        float x = (tid < nw) ? sbuf[tid] : -3.4e38f;
        #pragma unroll
        for (int o = 16; o > 0; o >>= 1) x = fmaxf(x, __shfl_down_sync(0xffffffffu, x, o));
        if (tid == 0) sbuf[0] = x;
    }
    __syncthreads();
    float r = sbuf[0];
    __syncthreads();
    return r;
}

// ===================== mma.sync GEMM =====================
// D[m0+r][c0+n] = alpha*(Ah·Bh^T + Ah·Bl^T + Al·Bh^T)[r][n] + cadd + bias[n]
// A (hi/lo): M x K bf16 row-major (lda); B (hi/lo): Npad x K bf16 row-major (ldb)
// C fp32 ldc; writes only n < Nreal. M mult of 128, K mult of 32.
// smem per stage: 4 matrices x 128 rows x 80B (row stride) = 40960B; x2 stages.
#define STG_MAT 10240
#define STG_SZ  40960
#define SMEM_GEMM (2*STG_SZ)

__global__ __launch_bounds__(256)
void mma_gemm(const bf16* __restrict__ Ah, const bf16* __restrict__ Al,
              const bf16* __restrict__ Bh, const bf16* __restrict__ Bl,
              const float* __restrict__ bias, float* __restrict__ C,
              int lda, int ldb, int ldc, int c0, int Nreal, int K,
              long long sA, long long sB, long long sC,
              float alpha, float cadd)
{
    extern __shared__ char smem[];
    int tid = threadIdx.x, w = tid >> 5, lane = tid & 31;
    long long bz = blockIdx.z;
    Ah += bz * sA; Al += bz * sA;
    Bh += bz * sB; Bl += bz * sB;
    C  += bz * sC;
    int m0 = blockIdx.y * 128, n0 = blockIdx.x * 128;
    const int NC = K >> 5;

    auto load_stage = [&](int kofs, int s) {
        char* stg = smem + s * STG_SZ;
        #pragma unroll
        for (int i = 0; i < 8; i++) {
            int idx = tid + i * 256;          // 0..2047
            int mat = idx >> 9;               // 0:Ah 1:Al 2:Bh 3:Bl
            int cc  = idx & 511;
            int row = cc >> 2, kc = cc & 3;
            uint32_t dst = smem_u32(stg + mat * STG_MAT + row * 80 + kc * 16);
            const bf16* p = (mat == 0) ? Ah : (mat == 1) ? Al : (mat == 2) ? Bh : Bl;
            int b0 = (mat < 2) ? m0 : n0;
            int ld = (mat < 2) ? lda : ldb;
            CP_ASYNC16(dst, p + (size_t)(b0 + row) * ld + kofs + kc * 8);
        }
        CP_COMMIT();
    };

    load_stage(0, 0);
    if (NC > 1) load_stage(32, 1);

    int g = lane >> 2, t = lane & 3;
    int wm = (w & 3) * 32, wn = (w >> 2) * 64;

    float acc[2][8][4];
    #pragma unroll
    for (int mt = 0; mt < 2; mt++)
        #pragma unroll
        for (int nt = 0; nt < 8; nt++)
            #pragma unroll
            for (int r = 0; r < 4; r++) acc[mt][nt][r] = 0.f;

    for (int kc = 0; kc < NC; kc++) {
        if (kc + 1 < NC) { CP_WAIT1(); } else { CP_WAIT0(); }
        __syncthreads();
        const char* stg = smem + (kc & 1) * STG_SZ;
        const char* pAh = stg;
        const char* pAl = stg + STG_MAT;
        const char* pBh = stg + 2 * STG_MAT;
        const char* pBl = stg + 3 * STG_MAT;

        #pragma unroll
        for (int ko = 0; ko < 32; ko += 16) {
            uint32_t aH[2][4], aL[2][4], b[8][2];
            #pragma unroll
            for (int mt = 0; mt < 2; mt++) {
                int r0 = (wm + mt * 16 + g) * 80 + (ko + t * 2) * 2;
                aH[mt][0] = *(const uint32_t*)(pAh + r0);
                aH[mt][1] = *(const uint32_t*)(pAh + r0 + 640);
                aH[mt][2] = *(const uint32_t*)(pAh + r0 + 16);
                aH[mt][3] = *(const uint32_t*)(pAh + r0 + 656);
                aL[mt][0] = *(const uint32_t*)(pAl + r0);
                aL[mt][1] = *(const uint32_t*)(pAl + r0 + 640);
                aL[mt][2] = *(const uint32_t*)(pAl + r0 + 16);
                aL[mt][3] = *(const uint32_t*)(pAl + r0 + 656);
            }
            // Bh pass: acc += Ah*Bh + Al*Bh
            #pragma unroll
            for (int nt = 0; nt < 8; nt++) {
                int r0 = (wn + nt * 8 + g) * 80 + (ko + t * 2) * 2;
                b[nt][0] = *(const uint32_t*)(pBh + r0);
                b[nt][1] = *(const uint32_t*)(pBh + r0 + 16);
            }
            #pragma unroll
            for (int mt = 0; mt < 2; mt++)
                #pragma unroll
                for (int nt = 0; nt < 8; nt++) {
                    mma16816(acc[mt][nt], aH[mt], b[nt]);
                    mma16816(acc[mt][nt], aL[mt], b[nt]);
                }
            // Bl pass: acc += Ah*Bl
            #pragma unroll
            for (int nt = 0; nt < 8; nt++) {
                int r0 = (wn + nt * 8 + g) * 80 + (ko + t * 2) * 2;
                b[nt][0] = *(const uint32_t*)(pBl + r0);
                b[nt][1] = *(const uint32_t*)(pBl + r0 + 16);
            }
            #pragma unroll
            for (int mt = 0; mt < 2; mt++)
                #pragma unroll
                for (int nt = 0; nt < 8; nt++)
                    mma16816(acc[mt][nt], aH[mt], b[nt]);
        }
        __syncthreads();
        if (kc + 2 < NC) load_stage((kc + 2) * 32, kc & 1);
    }

    // epilogue
    #pragma unroll
    for (int mt = 0; mt < 2; mt++) {
        int r0 = m0 + wm + mt * 16 + g;
        float* c0p = C + (size_t)r0 * ldc + c0;
        float* c1p = C + (size_t)(r0 + 8) * ldc + c0;
        #pragma unroll
        for (int nt = 0; nt < 8; nt++) {
            int n = n0 + wn + nt * 8 + t * 2;
            if (n < Nreal) {
                float bv = bias ? bias[n] : 0.f;
                c0p[n] = alpha * acc[mt][nt][0] + cadd + bv;
                c1p[n] = alpha * acc[mt][nt][2] + cadd + bv;
            }
            if (n + 1 < Nreal) {
                float bv = bias ? bias[n + 1] : 0.f;
                c0p[n + 1] = alpha * acc[mt][nt][1] + cadd + bv;
                c1p[n + 1] = alpha * acc[mt][nt][3] + cadd + bv;
            }
        }
    }
}

// ===================== transpose+split weights =====================
__global__ void k_tsplit(const float* __restrict__ W, bf16* __restrict__ Th,
                         bf16* __restrict__ Tl, int K, int N, int Kpad)
{
    __shared__ float t[32][33];
    int nb = blockIdx.x * 32, kb = blockIdx.y * 32;
    int tx = threadIdx.x, ty = threadIdx.y;
    #pragma unroll
    for (int i = 0; i < 32; i += 8) {
        int k = kb + ty + i, n = nb + tx;
        t[ty + i][tx] = (k < K && n < N) ? W[(size_t)k * N + n] : 0.f;
    }
    __syncthreads();
    #pragma unroll
    for (int i = 0; i < 32; i += 8) {
        int n = nb + ty + i, k = kb + tx;
        if (n < N && k < K) {
            float v = t[tx][ty + i];
            bf16 h, l; bsplit(v, h, l);
            Th[(size_t)n * Kpad + k] = h;
            Tl[(size_t)n * Kpad + k] = l;
        }
    }
}

// ===================== Lorentz layernorm -> hi/lo =====================
__global__ __launch_bounds__(256)
void k_ln(const float* __restrict__ x, const float* __restrict__ g,
          const float* __restrict__ b, bf16* __restrict__ oh, bf16* __restrict__ ol)
{
    __shared__ float sbuf[32];
    int t = blockIdx.x, tid = threadIdx.x;
    const float* xs = x + (size_t)t * 1024 + 1;
    float sv[4]; float s1 = 0.f, s2 = 0.f;
    #pragma unroll
    for (int j = 0; j < 4; j++) {
        int i = tid + j * 256;
        sv[j] = 0.f;
        if (i < 1023) { sv[j] = xs[i]; s1 += sv[j]; s2 += sv[j] * sv[j]; }
    }
    s1 = blk_sum(s1, sbuf);
    s2 = blk_sum(s2, sbuf);
    float mu = s1 * (1.f / 1023.f);
    float var = s2 * (1.f / 1023.f) - mu * mu;
    float rstd = rsqrtf(var + 1e-5f);
    float q = 0.f;
    float yv[4];
    #pragma unroll
    for (int j = 0; j < 4; j++) {
        int i = tid + j * 256;
        yv[j] = 0.f;
        if (i < 1023) {
            yv[j] = (sv[j] - mu) * rstd * g[i] + b[i];
            q += yv[j] * yv[j];
        }
    }
    q = blk_sum(q, sbuf);
    size_t base = (size_t)t * 1024;
    #pragma unroll
    for (int j = 0; j < 4; j++) {
        int i = tid + j * 256;
        if (i < 1023) {
            bf16 h, l; bsplit(yv[j], h, l);
            oh[base + 1 + i] = h; ol[base + 1 + i] = l;
        }
    }
    if (tid == 0) {
        bf16 h, l; bsplit(sqrtf(q + 1.f), h, l);
        oh[base] = h; ol[base] = l;
    }
}

// ===================== lift heads (q/k) =====================
__global__ __launch_bounds__(512)
void k_lift(const float* __restrict__ S, bf16* __restrict__ Oh, bf16* __restrict__ Ol, float sign)
{
    int t = blockIdx.x;
    int b = t >> 10, n = t & 1023;
    int w = threadIdx.x >> 5, lane = threadIdx.x & 31;
    const float* src = S + (size_t)t * 1024 + w * 64;
    float v0 = src[lane], v1 = src[lane + 32];
    float ss = v0 * v0 + v1 * v1;
    #pragma unroll
    for (int o = 16; o > 0; o >>= 1) ss += __shfl_down_sync(0xffffffffu, ss, o);
    ss = __shfl_sync(0xffffffffu, ss, 0);
    size_t base = ((size_t)(b * HH + w) * 1024 + n) * 128;
    bf16 h, l;
    bsplit(v0, h, l); Oh[base + 1 + lane] = h; Ol[base + 1 + lane] = l;
    bsplit(v1, h, l); Oh[base + 33 + lane] = h; Ol[base + 33 + lane] = l;
    if (lane == 0) {
        bsplit(sign * sqrtf(ss + 1.f), h, l);
        Oh[base] = h; Ol[base] = l;
    }
    if (w == 0) {
        // zero pad cols 65..127 (once per (bh,n) handled by warp 0's bh=first; need all)
    }
    // pad columns 65..127 for all heads: each warp pads its own row
    for (int i = 65 + lane; i < 128; i += 32) { Oh[base + i] = __float2bfloat16(0.f); Ol[base + i] = __float2bfloat16(0.f); }
}

// ===================== lift+transpose v =====================
__global__ void k_liftT(const float* __restrict__ vs, bf16* __restrict__ Th, bf16* __restrict__ Tl)
{
    int blk = blockIdx.x;
    int bh = blk >> 5;
    int tg = blk & 31;
    int b = bh >> 4, h = bh & 15;
    __shared__ float sv[32][65];
    __shared__ float stime[32];
    int tx = threadIdx.x, ty = threadIdx.y;
    #pragma unroll
    for (int i = 0; i < 32; i += 8) {
        int tok = i + ty;
        const float* src = vs + (size_t)(b * 1024 + tg * 32 + tok) * 1024 + h * 64;
        sv[tok][1 + tx] = src[tx];
        sv[tok][33 + tx] = src[tx + 32];
    }
    __syncthreads();
    if (ty == 0) {
        float s = 0.f;
        #pragma unroll
        for (int d = 1; d <= 64; d++) { float x = sv[tx][d]; s += x * x; }
        stime[tx] = sqrtf(s + 1.f);
    }
    __syncthreads();
    size_t base = (size_t)bh * (128 * 1024) + (size_t)(tg * 32);
    for (int d = ty; d < 128; d += 8) {
        float v = (d == 0) ? stime[tx] : (d < 65 ? sv[tx][d] : 0.f);
        bf16 hh, ll; bsplit(v, hh, ll);
        Th[base + (size_t)d * 1024 + tx] = hh;
        Tl[base + (size_t)d * 1024 + tx] = ll;
    }
}

// ===================== softmax -> probs hi/lo =====================
__global__ __launch_bounds__(256)
void k_softmax(const float* __restrict__ sc, bf16* __restrict__ ph, bf16* __restrict__ pl)
{
    __shared__ float sbuf[32];
    size_t off = (size_t)blockIdx.x * 1024;
    const float* row = sc + off;
    int tid = threadIdx.x;
    float v[4];
    float m = -3.4e38f;
    #pragma unroll
    for (int j = 0; j < 4; j++) { v[j] = row[tid + j * 256]; m = fmaxf(m, v[j]); }
    m = blk_max(m, sbuf);
    float s = 0.f;
    #pragma unroll
    for (int j = 0; j < 4; j++) { v[j] = __expf(v[j] - m); s += v[j]; }
    s = blk_sum(s, sbuf);
    float inv = 1.f / s;
    #pragma unroll
    for (int j = 0; j < 4; j++) {
        float p = v[j] * inv;
        bf16 h, l; bsplit(p, h, l);
        ph[off + tid + j * 256] = h;
        pl[off + tid + j * 256] = l;
    }
}

// ===================== normalize mid + concat =====================
__global__ __launch_bounds__(512)
void k_normcat(const float* __restrict__ mid, bf16* __restrict__ ch, bf16* __restrict__ cl)
{
    int t = blockIdx.x;
    int b = t >> 10, n = t & 1023;
    int w = threadIdx.x >> 5, lane = threadIdx.x & 31;
    const float* src = mid + ((size_t)(b * HH + w) * 1024 + n) * 65;
    float tmv = src[0];
    float a0 = src[1 + lane], a1 = src[33 + lane];
    float ss = a0 * a0 + a1 * a1;
    #pragma unroll
    for (int o = 16; o > 0; o >>= 1) ss += __shfl_down_sync(0xffffffffu, ss, o);
    ss = __shfl_sync(0xffffffffu, ss, 0);
    float inv = rsqrtf(fmaxf(tmv * tmv - ss, 1e-8f));
    size_t base = (size_t)t * 1088 + w * 65;
    bf16 h, l;
    bsplit(a0 * inv, h, l); ch[base + 1 + lane] = h; cl[base + 1 + lane] = l;
    bsplit(a1 * inv, h, l); ch[base + 33 + lane] = h; cl[base + 33 + lane] = l;
    if (lane == 0) { bsplit(tmv * inv, h, l); ch[base] = h; cl[base] = l; }
}

// ===================== gelu + lift =====================
__global__ __launch_bounds__(256)
void k_gelu(const float* __restrict__ fcpre, bf16* __restrict__ fh, bf16* __restrict__ fl)
{
    __shared__ float sbuf[32];
    int t = blockIdx.x, tid = threadIdx.x;
    const float* rin = fcpre + (size_t)t * 4095;
    float gv[16];
    float q = 0.f;
    #pragma unroll
    for (int j = 0; j < 16; j++) {
        int i = tid + j * 256;
        gv[j] = 0.f;
        if (i < 4095) {
            float x = rin[i];
            gv[j] = 0.5f * x * (1.f + erff(x * 0.70710678118654752f));
            q += gv[j] * gv[j];
        }
    }
    q = blk_sum(q, sbuf);
    size_t base = (size_t)t * 4096;
    #pragma unroll
    for (int j = 0; j < 16; j++) {
        int i = tid + j * 256;
        if (i < 4095) {
            bf16 h, l; bsplit(gv[j], h, l);
            fh[base + 1 + i] = h; fl[base + 1 + i] = l;
        }
    }
    if (tid == 0) {
        bf16 h, l; bsplit(sqrtf(q + 1.f), h, l);
        fh[base] = h; fl[base] = l;
    }
}

// ===================== Lorentz residual =====================
__global__ __launch_bounds__(256)
void k_lresnet(const float* __restrict__ xin, const float* __restrict__ spart,
               const float* __restrict__ wp, float* __restrict__ out)
{
    __shared__ float sbuf[32];
    int t = blockIdx.x, tid = threadIdx.x;
    float w = wp[0];
    const float* xr = xin + (size_t)t * 1024;
    const float* ar = spart + (size_t)t * 1023;
    float xs[4], as[4];
    float sa = 0.f;
    #pragma unroll
    for (int j = 0; j < 4; j++) {
        int i = tid + j * 256;
        xs[j] = 0.f; as[j] = 0.f;
        if (i < 1023) { xs[j] = xr[1 + i]; as[j] = ar[i]; sa += as[j] * as[j]; }
    }
    sa = blk_sum(sa, sbuf);
    float axt = sqrtf(sa + 1.f);
    float zt = xr[0] + w * axt;
    float sz = 0.f;
    #pragma unroll
    for (int j = 0; j < 4; j++) {
        int i = tid + j * 256;
        if (i < 1023) { xs[j] = xs[j] + w * as[j]; sz += xs[j] * xs[j]; }
    }
    sz = blk_sum(sz, sbuf);
    float inv = rsqrtf(fmaxf(zt * zt - sz, 1e-8f));
    if (tid == 0) out[(size_t)t * 1024] = zt * inv;
    #pragma unroll
    for (int j = 0; j < 4; j++) {
        int i = tid + j * 256;
        if (i < 1023) out[(size_t)t * 1024 + 1 + i] = xs[j] * inv;
    }
}

// ===================== host =====================
extern "C" void kernel_launch(void* const* d_in, const int* in_sizes, int n_in,
                              void* d_out, int out_size)
{
    const float* x   = (const float*)d_in[0];
    const float* g1  = (const float*)d_in[1];
    const float* b1  = (const float*)d_in[2];
    const float* Wq  = (const float*)d_in[3];
    const float* bq  = (const float*)d_in[4];
    const float* Wk  = (const float*)d_in[5];
    const float* bk  = (const float*)d_in[6];
    const float* Wv  = (const float*)d_in[7];
    const float* bv  = (const float*)d_in[8];
    const float* Wo  = (const float*)d_in[9];
    const float* bo  = (const float*)d_in[10];
    const float* g2  = (const float*)d_in[11];
    const float* b2  = (const float*)d_in[12];
    const float* Wfc = (const float*)d_in[13];
    const float* bfc = (const float*)d_in[14];
    const float* Wpj = (const float*)d_in[15];
    const float* bpj = (const float*)d_in[16];
    const float* w1  = (const float*)d_in[17];
    const float* w2  = (const float*)d_in[18];
    float* out = (float*)d_out;

    cudaFuncSetAttribute(mma_gemm, cudaFuncAttributeMaxDynamicSharedMemorySize, SMEM_GEMM);

    #define SYM(p, s) do { void* _t; cudaGetSymbolAddress(&_t, s); p = decltype(p)(_t); } while (0)
    bf16 *lxh, *lxl, *WqTh, *WqTl, *WkTh, *WkTl, *WvTh, *WvTl, *WoTh, *WoTl;
    bf16 *WfcTh, *WfcTl, *WpjTh, *WpjTl;
    bf16 *qhh, *qhl, *khh, *khl, *vTh, *vTl, *ph, *pl, *cath, *catl, *h1h, *h1l, *fch, *fcl;
    float *qs, *ks, *vs, *sc, *mid, *axs, *x1, *fcpre, *pjs;
    SYM(lxh, g_lxh); SYM(lxl, g_lxl);
    SYM(WqTh, g_WqTh); SYM(WqTl, g_WqTl);
    SYM(WkTh, g_WkTh); SYM(WkTl, g_WkTl);
    SYM(WvTh, g_WvTh); SYM(WvTl, g_WvTl);
    SYM(WoTh, g_WoTh); SYM(WoTl, g_WoTl);
    SYM(WfcTh, g_WfcTh); SYM(WfcTl, g_WfcTl);
    SYM(WpjTh, g_WpjTh); SYM(WpjTl, g_WpjTl);
    SYM(qs, g_qs); SYM(ks, g_ks); SYM(vs, g_vs);
    SYM(qhh, g_qhh); SYM(qhl, g_qhl); SYM(khh, g_khh); SYM(khl, g_khl);
    SYM(vTh, g_vTh); SYM(vTl, g_vTl);
    SYM(sc, g_sc); SYM(ph, g_ph); SYM(pl, g_pl);
    SYM(mid, g_mid); SYM(cath, g_cath); SYM(catl, g_catl);
    SYM(axs, g_axs); SYM(x1, g_x1); SYM(h1h, g_h1h); SYM(h1l, g_h1l);
    SYM(fcpre, g_fcpre); SYM(fch, g_fch); SYM(fcl, g_fcl); SYM(pjs, g_pjs);

    dim3 tb(32, 8);
    // weight transposes (K, N, Kpad)
    k_tsplit<<<dim3(32, 32), tb>>>(Wq, WqTh, WqTl, 1024, 1024, 1024);
    k_tsplit<<<dim3(32, 32), tb>>>(Wk, WkTh, WkTl, 1024, 1024, 1024);
    k_tsplit<<<dim3(32, 32), tb>>>(Wv, WvTh, WvTl, 1024, 1024, 1024);
    k_tsplit<<<dim3(32, 33), tb>>>(Wo, WoTh, WoTl, 1040, 1023, 1088);
    k_tsplit<<<dim3(128, 32), tb>>>(Wfc, WfcTh, WfcTl, 1024, 4095, 1024);
    k_tsplit<<<dim3(32, 128), tb>>>(Wpj, WpjTh, WpjTl, 4096, 1023, 4096);

    // LN1
    k_ln<<<TT, 256>>>(x, g1, b1, lxh, lxl);

    // QKV
    {
        dim3 grid(8, 32, 1);
        mma_gemm<<<grid, 256, SMEM_GEMM>>>(lxh, lxl, WqTh, WqTl, bq, qs,
            1024, 1024, 1024, 0, 1024, 1024, 0, 0, 0, 1.f, 0.f);
        mma_gemm<<<grid, 256, SMEM_GEMM>>>(lxh, lxl, WkTh, WkTl, bk, ks,
            1024, 1024, 1024, 0, 1024, 1024, 0, 0, 0, 1.f, 0.f);
        mma_gemm<<<grid, 256, SMEM_GEMM>>>(lxh, lxl, WvTh, WvTl, bv, vs,
            1024, 1024, 1024, 0, 1024, 1024, 0, 0, 0, 1.f, 0.f);
    }

    // lifts
    k_lift<<<TT, 512>>>(qs, qhh, qhl, -1.f);
    k_lift<<<TT, 512>>>(ks, khh, khl, 1.f);
    k_liftT<<<BHN * 32, tb>>>(vs, vTh, vTl);

    // scores = 0.25 + 0.25*<q',k'>  (K=128; cols 65..127 are zero pads)
    mma_gemm<<<dim3(8, 8, BHN), 256, SMEM_GEMM>>>(qhh, qhl, khh, khl, nullptr, sc,
        128, 128, 1024, 0, 1024, 128,
        (long long)1024 * 128, (long long)1024 * 128, (long long)1024 * 1024,
        0.25f, 0.25f);

    // softmax -> probs hi/lo
    k_softmax<<<BHN * 1024, 256>>>(sc, ph, pl);

    // mid = probs @ v_lift
    mma_gemm<<<dim3(1, 8, BHN), 256, SMEM_GEMM>>>(ph, pl, vTh, vTl, nullptr, mid,
        1024, 1024, 65, 0, 65, 1024,
        (long long)1024 * 1024, (long long)128 * 1024, (long long)1024 * 65,
        1.f, 0.f);

    // normalize + concat
    k_normcat<<<TT, 512>>>(mid, cath, catl);

    // Wo
    mma_gemm<<<dim3(8, 32, 1), 256, SMEM_GEMM>>>(cath, catl, WoTh, WoTl, bo, axs,
        1088, 1088, 1023, 0, 1023, 1088, 0, 0, 0, 1.f, 0.f);

    // residual 1
    k_lresnet<<<TT, 256>>>(x, axs, w1, x1);

    // LN2
    k_ln<<<TT, 256>>>(x1, g2, b2, h1h, h1l);

    // Wfc
    mma_gemm<<<dim3(32, 32, 1), 256, SMEM_GEMM>>>(h1h, h1l, WfcTh, WfcTl, bfc, fcpre,
        1024, 1024, 4095, 0, 4095, 1024, 0, 0, 0, 1.f, 0.f);

    // gelu + lift
    k_gelu<<<TT, 256>>>(fcpre, fch, fcl);

    // Wpj
    mma_gemm<<<dim3(8, 32, 1), 256, SMEM_GEMM>>>(fch, fcl, WpjTh, WpjTl, bpj, pjs,
        4096, 4096, 1023, 0, 1023, 4096, 0, 0, 0, 1.f, 0.f);

    // residual 2
    k_lresnet<<<TT, 256>>>(x1, pjs, w2, out);
}